// round 1
// baseline (speedup 1.0000x reference)
#include <cuda_runtime.h>

#define BATCH 16
#define T 1024
#define D 256
#define BM 128
#define BN 128
#define BK 16
#define KT (D / BK)   // 16 k-tiles

// Scratch for bias terms (allocation-free rule: __device__ globals)
__device__ float g_bias_x[BATCH * T];
__device__ float g_bias_y[BATCH * T];

__device__ __forceinline__ unsigned long long pack2(float lo, float hi) {
    unsigned long long r;
    asm("mov.b64 %0, {%1, %2};" : "=l"(r) : "f"(lo), "f"(hi));
    return r;
}
__device__ __forceinline__ void unpack2(unsigned long long v, float& lo, float& hi) {
    asm("mov.b64 {%0, %1}, %2;" : "=f"(lo), "=f"(hi) : "l"(v));
}
// Packed dual-FMA: d.lo = a.lo*b.lo + c.lo ; d.hi = a.hi*b.hi + c.hi
// ptxas will NOT auto-fuse this from C++; must come from PTX fma.rn.f32x2.
__device__ __forceinline__ unsigned long long ffma2(unsigned long long a,
                                                    unsigned long long b,
                                                    unsigned long long c) {
    unsigned long long d;
    asm("fma.rn.f32x2 %0, %1, %2, %3;" : "=l"(d) : "l"(a), "l"(b), "l"(c));
    return d;
}

// One warp per row: bias_x[b,i] = dot(x[b,i,:], w1), bias_y[b,j] = dot(y[b,j,:], w2)
__global__ void bias_kernel(const float* __restrict__ x, const float* __restrict__ y,
                            const float* __restrict__ WS) {
    int warp = blockIdx.x * (blockDim.x >> 5) + (threadIdx.x >> 5);
    int lane = threadIdx.x & 31;
    const int nrows = BATCH * T;
    const float* src;
    const float* w;
    float* dst;
    int row;
    if (warp < nrows) { src = x; w = WS;     dst = g_bias_x; row = warp; }
    else              { src = y; w = WS + D; dst = g_bias_y; row = warp - nrows; }
    const float4* p4 = (const float4*)(src + (size_t)row * D);
    const float4* w4 = (const float4*)w;
    float4 v0 = p4[lane], v1 = p4[lane + 32];
    float4 a0 = w4[lane], a1 = w4[lane + 32];
    float s = v0.x * a0.x + v0.y * a0.y + v0.z * a0.z + v0.w * a0.w
            + v1.x * a1.x + v1.y * a1.y + v1.z * a1.z + v1.w * a1.w;
#pragma unroll
    for (int o = 16; o; o >>= 1) s += __shfl_xor_sync(0xffffffffu, s, o);
    if (lane == 0) dst[row] = s;
}

// 128x128 tile GEMM: C[b] = (x[b] * w3) @ y[b]^T + bias_x[b,i] + bias_y[b,j]
__global__ void __launch_bounds__(256) gemm_kernel(
    const float* __restrict__ x, const float* __restrict__ y,
    const float* __restrict__ WS, float* __restrict__ out) {
    __shared__ __align__(16) float As[2][BK][BM];
    __shared__ __align__(16) float Bs[2][BK][BN];

    const int b = blockIdx.z;
    const int tile_m = blockIdx.y * BM;
    const int tile_n = blockIdx.x * BN;

    const float* A  = x + (size_t)b * T * D;
    const float* Bg = y + (size_t)b * T * D;
    const float* w3 = WS + 2 * D;
    float* C = out + (size_t)b * T * T;

    const int tid = threadIdx.x;
    // Loader mapping: 2 threads per row, each stages 8 contiguous k (2x float4)
    const int ld_row = tid >> 1;        // 0..127
    const int ld_k8  = (tid & 1) * 8;   // 0 or 8

    const float* Agp = A  + (size_t)(tile_m + ld_row) * D + ld_k8;
    const float* Bgp = Bg + (size_t)(tile_n + ld_row) * D + ld_k8;
    const float* w3p = w3 + ld_k8;

    // Compute mapping: 16x16 threads, 8x8 outputs each (4+4 split rows/cols)
    const int tx = tid & 15, ty = tid >> 4;
    const int m0 = ty * 4, m1 = ty * 4 + 64;
    const int n0 = tx * 4, n1 = tx * 4 + 64;

    unsigned long long acc[8][4];
#pragma unroll
    for (int i = 0; i < 8; i++)
#pragma unroll
        for (int j = 0; j < 4; j++) acc[i][j] = 0ull;

    float4 ra0, ra1, rb0, rb1;

    auto stage_tile = [&](int kt) {
        const float* ap = Agp + kt * BK;
        const float* bp = Bgp + kt * BK;
        ra0 = *(const float4*)(ap + 0);
        ra1 = *(const float4*)(ap + 4);
        rb0 = *(const float4*)(bp + 0);
        rb1 = *(const float4*)(bp + 4);
        float4 w0 = *(const float4*)(w3p + kt * BK + 0);
        float4 w1 = *(const float4*)(w3p + kt * BK + 4);
        ra0.x *= w0.x; ra0.y *= w0.y; ra0.z *= w0.z; ra0.w *= w0.w;
        ra1.x *= w1.x; ra1.y *= w1.y; ra1.z *= w1.z; ra1.w *= w1.w;
    };
    auto store_tile = [&](int sbuf) {
        As[sbuf][ld_k8 + 0][ld_row] = ra0.x;
        As[sbuf][ld_k8 + 1][ld_row] = ra0.y;
        As[sbuf][ld_k8 + 2][ld_row] = ra0.z;
        As[sbuf][ld_k8 + 3][ld_row] = ra0.w;
        As[sbuf][ld_k8 + 4][ld_row] = ra1.x;
        As[sbuf][ld_k8 + 5][ld_row] = ra1.y;
        As[sbuf][ld_k8 + 6][ld_row] = ra1.z;
        As[sbuf][ld_k8 + 7][ld_row] = ra1.w;
        Bs[sbuf][ld_k8 + 0][ld_row] = rb0.x;
        Bs[sbuf][ld_k8 + 1][ld_row] = rb0.y;
        Bs[sbuf][ld_k8 + 2][ld_row] = rb0.z;
        Bs[sbuf][ld_k8 + 3][ld_row] = rb0.w;
        Bs[sbuf][ld_k8 + 4][ld_row] = rb1.x;
        Bs[sbuf][ld_k8 + 5][ld_row] = rb1.y;
        Bs[sbuf][ld_k8 + 6][ld_row] = rb1.z;
        Bs[sbuf][ld_k8 + 7][ld_row] = rb1.w;
    };

    stage_tile(0);
    store_tile(0);
    __syncthreads();

    int buf = 0;
#pragma unroll 1
    for (int kt = 0; kt < KT; ++kt) {
        if (kt + 1 < KT) stage_tile(kt + 1);  // global loads in flight over compute

#pragma unroll
        for (int k = 0; k < BK; ++k) {
            float4 a0 = *(const float4*)&As[buf][k][m0];
            float4 a1 = *(const float4*)&As[buf][k][m1];
            ulonglong2 bb0 = *(const ulonglong2*)&Bs[buf][k][n0];
            ulonglong2 bb1 = *(const ulonglong2*)&Bs[buf][k][n1];
            unsigned long long bv[4] = {bb0.x, bb0.y, bb1.x, bb1.y};
            float am[8] = {a0.x, a0.y, a0.z, a0.w, a1.x, a1.y, a1.z, a1.w};
#pragma unroll
            for (int mi = 0; mi < 8; mi++) {
                unsigned long long av = pack2(am[mi], am[mi]);
#pragma unroll
                for (int j = 0; j < 4; j++) acc[mi][j] = ffma2(av, bv[j], acc[mi][j]);
            }
        }

        if (kt + 1 < KT) {
            store_tile(buf ^ 1);  // other buffer: no pre-sync needed
            __syncthreads();
            buf ^= 1;
        }
    }

    // Epilogue: add rank-1 biases, vectorized stores
    float bx[8], by[8];
#pragma unroll
    for (int i = 0; i < 4; i++) {
        bx[i]     = g_bias_x[b * T + tile_m + m0 + i];
        bx[4 + i] = g_bias_x[b * T + tile_m + m1 + i];
        by[i]     = g_bias_y[b * T + tile_n + n0 + i];
        by[4 + i] = g_bias_y[b * T + tile_n + n1 + i];
    }
#pragma unroll
    for (int mi = 0; mi < 8; mi++) {
        int row = (mi < 4) ? (tile_m + m0 + mi) : (tile_m + m1 + (mi - 4));
        float o[8];
        unpack2(acc[mi][0], o[0], o[1]);
        unpack2(acc[mi][1], o[2], o[3]);
        unpack2(acc[mi][2], o[4], o[5]);
        unpack2(acc[mi][3], o[6], o[7]);
        float bias = bx[mi];
        float4 v0 = make_float4(o[0] + bias + by[0], o[1] + bias + by[1],
                                o[2] + bias + by[2], o[3] + bias + by[3]);
        float4 v1 = make_float4(o[4] + bias + by[4], o[5] + bias + by[5],
                                o[6] + bias + by[6], o[7] + bias + by[7]);
        *(float4*)&C[(size_t)row * T + tile_n + n0] = v0;
        *(float4*)&C[(size_t)row * T + tile_n + n1] = v1;
    }
}

extern "C" void kernel_launch(void* const* d_in, const int* in_sizes, int n_in,
                              void* d_out, int out_size) {
    const float* x  = (const float*)d_in[0];
    const float* y  = (const float*)d_in[1];
    const float* WS = (const float*)d_in[2];
    float* out = (float*)d_out;

    // 2*BATCH*T rows, 1 warp each, 8 warps per 256-thread block -> 4096 blocks
    bias_kernel<<<(2 * BATCH * T) / 8, 256>>>(x, y, WS);

    dim3 grid(T / BN, T / BM, BATCH);  // (8, 8, 16)
    gemm_kernel<<<grid, 256>>>(x, y, WS, out);
}

// round 3
// speedup vs baseline: 2.7369x; 2.7369x over previous
#include <cuda_runtime.h>
#include <cstdint>

#define BATCH 16
#define T 1024
#define D 256
#define BM 128
#define BN 128
#define BK 32
#define NCH (D / BK)   // 8 chunks
#define PAD 36         // padded row stride (floats) -> conflict-free fragment LDS

// Scratch (allocation-free rule: __device__ globals)
__device__ float g_xs[(size_t)BATCH * T * D];   // x * w3
__device__ float g_bias_x[BATCH * T];
__device__ float g_bias_y[BATCH * T];

__device__ __forceinline__ uint32_t to_tf32(float f) {
    uint32_t r;
    asm("cvt.rna.tf32.f32 %0, %1;" : "=r"(r) : "f"(f));
    return r;
}

__device__ __forceinline__ void mma_tf32(float (&d)[4], const uint32_t (&a)[4],
                                         const uint32_t (&b)[2]) {
    asm volatile(
        "mma.sync.aligned.m16n8k8.row.col.f32.tf32.tf32.f32 "
        "{%0,%1,%2,%3}, {%4,%5,%6,%7}, {%8,%9}, {%0,%1,%2,%3};"
        : "+f"(d[0]), "+f"(d[1]), "+f"(d[2]), "+f"(d[3])
        : "r"(a[0]), "r"(a[1]), "r"(a[2]), "r"(a[3]), "r"(b[0]), "r"(b[1]));
}

// ---------------- prescale + bias kernel ----------------
__global__ void __launch_bounds__(256) prep_kernel(
    const float* __restrict__ x, const float* __restrict__ y, const float* __restrict__ WS) {
    int warp = blockIdx.x * 8 + (threadIdx.x >> 5);
    int lane = threadIdx.x & 31;
    const int nrows = BATCH * T;
    if (warp < nrows) {
        const float4* p4 = (const float4*)(x + (size_t)warp * D);
        const float4* w1 = (const float4*)WS;
        const float4* w3 = (const float4*)(WS + 2 * D);
        float4* xs4 = (float4*)(g_xs + (size_t)warp * D);
        float s = 0.f;
#pragma unroll
        for (int i = 0; i < 2; i++) {
            int idx = lane + i * 32;
            float4 v = p4[idx], a = w1[idx], c = w3[idx];
            s += v.x * a.x + v.y * a.y + v.z * a.z + v.w * a.w;
            xs4[idx] = make_float4(v.x * c.x, v.y * c.y, v.z * c.z, v.w * c.w);
        }
#pragma unroll
        for (int o = 16; o; o >>= 1) s += __shfl_xor_sync(0xffffffffu, s, o);
        if (lane == 0) g_bias_x[warp] = s;
    } else {
        int row = warp - nrows;
        const float4* p4 = (const float4*)(y + (size_t)row * D);
        const float4* w2 = (const float4*)(WS + D);
        float s = 0.f;
#pragma unroll
        for (int i = 0; i < 2; i++) {
            int idx = lane + i * 32;
            float4 v = p4[idx], a = w2[idx];
            s += v.x * a.x + v.y * a.y + v.z * a.z + v.w * a.w;
        }
#pragma unroll
        for (int o = 16; o; o >>= 1) s += __shfl_xor_sync(0xffffffffu, s, o);
        if (lane == 0) g_bias_y[row] = s;
    }
}

// ---------------- tf32 warp-MMA GEMM ----------------
// C[b, i, j] = sum_k xs[b,i,k] * y[b,j,k] + bias_x[b,i] + bias_y[b,j]
// SMEM: As[2][128][PAD] + Bs[2][128][PAD] as uint32 (tf32 bit patterns)
#define SM_BUF (BM * PAD)                    // 4608 words per buffer
#define SMEM_WORDS (4 * SM_BUF)              // A0 A1 B0 B1
#define SMEM_BYTES (SMEM_WORDS * 4)          // 73728 B

__global__ void __launch_bounds__(256) gemm_mma_kernel(
    const float* __restrict__ y, float* __restrict__ out) {
    extern __shared__ uint32_t sm[];
    uint32_t* As = sm;                 // [2][BM][PAD]
    uint32_t* Bs = sm + 2 * SM_BUF;    // [2][BN][PAD]

    const int tid = threadIdx.x;
    const int wid = tid >> 5, lane = tid & 31;
    const int b = blockIdx.z;
    const int tile_m = blockIdx.y * BM;
    const int tile_n = blockIdx.x * BN;

    const float* A  = g_xs + ((size_t)b * T + tile_m) * D;
    const float* Bg = y    + ((size_t)b * T + tile_n) * D;

    // Warp layout: 2 (m) x 4 (n); warp tile 64 x 32
    const int warp_m = (wid >> 2) * 64;
    const int warp_n = (wid & 3) * 32;
    const int gid = lane >> 2;     // 0..7
    const int ctg = lane & 3;      // 0..3

    float acc[4][4][4];            // [mfrag][nfrag][reg]
#pragma unroll
    for (int i = 0; i < 4; i++)
#pragma unroll
        for (int j = 0; j < 4; j++)
#pragma unroll
            for (int r = 0; r < 4; r++) acc[i][j][r] = 0.f;

    // Staging: each thread loads 4 float4 per operand per chunk.
    // row = tid>>3 + 32*i, kq = tid&7 (float4 index within 32-wide k row)
    const int st_row = tid >> 3;
    const int st_kq  = tid & 7;
    float4 pa[4], pb[4];

    auto gload = [&](int chunk) {
        const float* ap = A  + chunk * BK + st_kq * 4;
        const float* bp = Bg + chunk * BK + st_kq * 4;
#pragma unroll
        for (int i = 0; i < 4; i++) {
            pa[i] = *(const float4*)(ap + (size_t)(st_row + 32 * i) * D);
            pb[i] = *(const float4*)(bp + (size_t)(st_row + 32 * i) * D);
        }
    };
    auto sts = [&](int buf) {
        uint32_t* ab = As + buf * SM_BUF;
        uint32_t* bb = Bs + buf * SM_BUF;
#pragma unroll
        for (int i = 0; i < 4; i++) {
            int off = (st_row + 32 * i) * PAD + st_kq * 4;
            uint4 va = make_uint4(to_tf32(pa[i].x), to_tf32(pa[i].y),
                                  to_tf32(pa[i].z), to_tf32(pa[i].w));
            uint4 vb = make_uint4(to_tf32(pb[i].x), to_tf32(pb[i].y),
                                  to_tf32(pb[i].z), to_tf32(pb[i].w));
            *(uint4*)(ab + off) = va;
            *(uint4*)(bb + off) = vb;
        }
    };

    gload(0);
    sts(0);
    __syncthreads();

#pragma unroll 1
    for (int c = 0; c < NCH; c++) {
        if (c + 1 < NCH) gload(c + 1);

        const uint32_t* ab = As + (c & 1) * SM_BUF;
        const uint32_t* bb = Bs + (c & 1) * SM_BUF;
#pragma unroll
        for (int ks = 0; ks < 4; ks++) {
            const int k0 = ks * 8;
            uint32_t af[4][4], bf[4][2];
#pragma unroll
            for (int mf = 0; mf < 4; mf++) {
                int m = warp_m + mf * 16 + gid;
                af[mf][0] = ab[m * PAD + k0 + ctg];
                af[mf][1] = ab[(m + 8) * PAD + k0 + ctg];
                af[mf][2] = ab[m * PAD + k0 + ctg + 4];
                af[mf][3] = ab[(m + 8) * PAD + k0 + ctg + 4];
            }
#pragma unroll
            for (int nf = 0; nf < 4; nf++) {
                int n = warp_n + nf * 8 + gid;
                bf[nf][0] = bb[n * PAD + k0 + ctg];
                bf[nf][1] = bb[n * PAD + k0 + ctg + 4];
            }
#pragma unroll
            for (int mf = 0; mf < 4; mf++)
#pragma unroll
                for (int nf = 0; nf < 4; nf++) mma_tf32(acc[mf][nf], af[mf], bf[nf]);
        }

        if (c + 1 < NCH) {
            sts((c + 1) & 1);
            __syncthreads();
        }
    }

    // Epilogue: + bias_x[row] + bias_y[col], float2 stores
    const float* bxp = g_bias_x + b * T + tile_m + warp_m;
    const float* byp = g_bias_y + b * T + tile_n + warp_n;
    float2 by[4];
#pragma unroll
    for (int nf = 0; nf < 4; nf++)
        by[nf] = *(const float2*)(byp + nf * 8 + ctg * 2);

#pragma unroll
    for (int mf = 0; mf < 4; mf++) {
        int r0 = warp_m + mf * 16 + gid;
        float bx0 = bxp[mf * 16 + gid];
        float bx1 = bxp[mf * 16 + gid + 8];
        float* C0 = out + ((size_t)b * T + tile_m + r0) * T + tile_n + warp_n;
        float* C1 = C0 + 8 * T;
#pragma unroll
        for (int nf = 0; nf < 4; nf++) {
            int coff = nf * 8 + ctg * 2;
            float2 v0 = make_float2(acc[mf][nf][0] + bx0 + by[nf].x,
                                    acc[mf][nf][1] + bx0 + by[nf].y);
            float2 v1 = make_float2(acc[mf][nf][2] + bx1 + by[nf].x,
                                    acc[mf][nf][3] + bx1 + by[nf].y);
            *(float2*)(C0 + coff) = v0;
            *(float2*)(C1 + coff) = v1;
        }
    }
}

extern "C" void kernel_launch(void* const* d_in, const int* in_sizes, int n_in,
                              void* d_out, int out_size) {
    const float* x  = (const float*)d_in[0];
    const float* y  = (const float*)d_in[1];
    const float* WS = (const float*)d_in[2];
    float* out = (float*)d_out;

    cudaFuncSetAttribute(gemm_mma_kernel, cudaFuncAttributeMaxDynamicSharedMemorySize, SMEM_BYTES);

    prep_kernel<<<(2 * BATCH * T) / 8, 256>>>(x, y, WS);

    dim3 grid(T / BN, T / BM, BATCH);   // (8, 8, 16)
    gemm_mma_kernel<<<grid, 256, SMEM_BYTES>>>(y, out);
}